// round 15
// baseline (speedup 1.0000x reference)
#include <cuda_runtime.h>
#include <cuda_fp16.h>

#define NN 50000
#define NE 1600000
#define DD 32
static constexpr float Hstep = 0.1f;

// ---------------- static device scratch ----------------
__device__ int      g_is64;
__device__ int      g_deg[2][NN];
__device__ int      g_cur[2][NN];
__device__ int      g_rowptr[2][NN + 1];
__device__ __align__(16) unsigned g_colval[2][NE];   // low16 = col, high16 = fp16 val
__device__ float    g_dis[2][NN];
__device__ __align__(16) __half g_tmph[2][2 * NN * DD];  // ping-pong y buffers
__device__ __align__(128) float g_x[2 * NN * DD];
__device__ __align__(128) float g_ksum[2 * NN * DD];
__device__ unsigned g_bar_cnt;
__device__ unsigned g_bar_gen;
__device__ int      g_q[80];            // work cursors: ((step*4+s)<<1)|br

// ---------------- edge readers (dtype-agnostic) ----------------
__device__ __forceinline__ int edge_src(const void* ei, int e, int is64) {
    if (is64) return (int)((const long long*)ei)[e];
    return ((const int*)ei)[e];
}
__device__ __forceinline__ int edge_dst(const void* ei, int e, int is64) {
    if (is64) return (int)((const long long*)ei)[NE + e];
    return ((const int*)ei)[NE + e];
}

// ---------------- setup: probe dtype + zero degree/barrier/queues ----------------
__global__ void k_probe_zero(const int* __restrict__ w) {
    if (blockIdx.x == 0) {
        __shared__ int anynz;
        if (threadIdx.x == 0) anynz = 0;
        __syncthreads();
        if (w[2 * threadIdx.x + 1] != 0) atomicOr(&anynz, 1);
        __syncthreads();
        if (threadIdx.x == 0) {
            g_is64 = (anynz == 0) ? 1 : 0;
            g_bar_cnt = 0;
            g_bar_gen = 0;
        }
        if (threadIdx.x < 80) g_q[threadIdx.x] = 0;
    }
    int i = blockIdx.x * blockDim.x + threadIdx.x;
    int stride = gridDim.x * blockDim.x;
    for (; i < 2 * NN; i += stride) ((int*)g_deg)[i] = 0;
}

// both branches: blocks [0,H) -> pos, [H,2H) -> neg
__global__ void k_hist(const void* __restrict__ epos, const void* __restrict__ eneg) {
    const int H = gridDim.x >> 1;
    const int br = blockIdx.x >= H;
    const void* ei = br ? eneg : epos;
    const int bb = blockIdx.x - br * H;
    const int is64 = g_is64;
    int stride = H * blockDim.x;
    for (int e = bb * blockDim.x + threadIdx.x; e < NE; e += stride)
        atomicAdd(&g_deg[br][edge_dst(ei, e, is64)], 1);
}

// block b = branch b: dis + exclusive scan -> rowptr, cur
__global__ void k_scan_dis() {
    const int b = blockIdx.x;
    __shared__ int sm[1024];
    const int tid = threadIdx.x;
    const int CH = (NN + 1023) / 1024;  // 49
    int base = tid * CH;
    int s = 0;
    for (int i = 0; i < CH; i++) {
        int idx = base + i;
        if (idx < NN) {
            int d = g_deg[b][idx];
            g_dis[b][idx] = rsqrtf((float)d + 1.0f);
            s += d;
        }
    }
    sm[tid] = s;
    __syncthreads();
    for (int off = 1; off < 1024; off <<= 1) {
        int v = (tid >= off) ? sm[tid - off] : 0;
        __syncthreads();
        sm[tid] += v;
        __syncthreads();
    }
    int run = (tid == 0) ? 0 : sm[tid - 1];
    for (int i = 0; i < CH; i++) {
        int idx = base + i;
        if (idx < NN) {
            g_rowptr[b][idx] = run;
            g_cur[b][idx] = run;
            run += g_deg[b][idx];
        }
    }
    if (tid == 1023) g_rowptr[b][NN] = sm[1023];
}

// blocks [0,EB): scatter pos; [EB,2EB): scatter neg; rest: init x / tin
__global__ void __launch_bounds__(256) k_scatter_init(
    const void* __restrict__ epos, const void* __restrict__ eneg,
    const float* __restrict__ x0, int EB) {
    if (blockIdx.x < 2 * EB) {
        const int br = blockIdx.x >= EB;
        const void* ei = br ? eneg : epos;
        const int bb = blockIdx.x - br * EB;
        const int is64 = g_is64;
        int stride = EB * blockDim.x;
        for (int e = bb * blockDim.x + threadIdx.x; e < NE; e += stride) {
            int s = edge_src(ei, e, is64);
            int d = edge_dst(ei, e, is64);
            int p = atomicAdd(&g_cur[br][d], 1);
            __half hv = __float2half(g_dis[br][s] * g_dis[br][d]);
            g_colval[br][p] = (unsigned)s | ((unsigned)__half_as_ushort(hv) << 16);
        }
    } else {
        int i = (blockIdx.x - 2 * EB) * blockDim.x + threadIdx.x;
        int stride = (gridDim.x - 2 * EB) * blockDim.x;
        for (; i < 2 * NN * DD; i += stride) {
            float v = x0[i >= NN * DD ? i - NN * DD : i];
            g_x[i] = v;
            g_tmph[0][i] = __float2half(v);
        }
    }
}

__device__ __forceinline__ void acc_edge(float4& acc, unsigned cvw, const uint2 rw_u) {
    union { uint2 u; __half2 h[2]; } rw;
    rw.u = rw_u;
    const float v = __half2float(__ushort_as_half((unsigned short)(cvw >> 16)));
    float2 a01 = __half22float2(rw.h[0]);
    float2 a23 = __half22float2(rw.h[1]);
    acc.x += v * a01.x; acc.y += v * a01.y;
    acc.z += v * a23.x; acc.w += v * a23.y;
}

// software grid barrier (all gridDim.x blocks co-resident)
__device__ __forceinline__ void grid_barrier() {
    __syncthreads();
    if (threadIdx.x == 0) {
        __threadfence();
        unsigned gen = *(volatile unsigned*)&g_bar_gen;
        unsigned a = atomicAdd(&g_bar_cnt, 1u);
        if (a == gridDim.x - 1) {
            g_bar_cnt = 0;
            __threadfence();
            *(volatile unsigned*)&g_bar_gen = gen + 1;
        } else {
            while (*(volatile unsigned*)&g_bar_gen == gen) __nanosleep(64);
            __threadfence();
        }
    }
    __syncthreads();
}

// ---------------- persistent fused RK4 ODE kernel ----------------
__global__ void __launch_bounds__(256, 4) k_ode(
    const float* __restrict__ Wp, const float* __restrict__ bp, const float* __restrict__ wtp,
    const float* __restrict__ Wn, const float* __restrict__ bn, const float* __restrict__ wtn,
    float* __restrict__ out) {
    const int H = gridDim.x >> 1;
    const int br = blockIdx.x >= H;
    const float* __restrict__ W = br ? Wn : Wp;
    const float* __restrict__ bvec = br ? bn : bp;
    const float* __restrict__ wt = br ? wtn : wtp;
    const unsigned* __restrict__ colval = g_colval[br];
    const int* __restrict__ rowptr = g_rowptr[br];
    const float* __restrict__ dis = g_dis[br];
    const size_t boff = (size_t)br * NN * DD;
    float* __restrict__ xw = g_x + boff;
    float* __restrict__ ksb = g_ksum + boff;

    __shared__ float Wt[DD * 36];
    __shared__ float zbuf[8][DD];
    for (int idx = threadIdx.x; idx < DD * DD; idx += 256) {
        int d = idx >> 5, l = idx & 31;
        Wt[l * 36 + d] = W[idx];
    }
    __syncthreads();

    const int lane = threadIdx.x & 31;
    const int wid = threadIdx.x >> 5;
    const int li = lane & 7;
    const int g = lane >> 3;
    const float bb = __ldg(&bvec[lane]);
    const float wtl = __ldg(&wt[lane]);

    int pin = 0;
    for (int step = 0; step < 10; step++) {
        const float tb = step * Hstep;
#pragma unroll 1
        for (int s = 0; s < 4; s++) {
            const float tcur = tb + ((s == 0) ? 0.f : (s == 3) ? Hstep : 0.5f * Hstep);
            const float gate = 1.0f / (1.0f + __expf(-tcur * wtl));
            const bool final_out = (step == 9) && (s == 3);
            const uint2* __restrict__ tin_v =
                (const uint2*)(g_tmph[pin]) + (size_t)br * NN * 8;
            __half* __restrict__ tout = g_tmph[pin ^ 1] + boff;
            int* qp = &g_q[((step * 4 + s) << 1) | br];

            for (;;) {
                int base;
                if (lane == 0) base = atomicAdd(qp, 8);
                base = __shfl_sync(0xffffffffu, base, 0);
                if (base >= NN) break;
                const int rend = (base + 8 < NN) ? base + 8 : NN;
                for (int r = base; r < rend; r++) {
                    const int st = rowptr[r];
                    const int en = rowptr[r + 1];
                    float4 acc = make_float4(0.f, 0.f, 0.f, 0.f);

                    int pre = en - st;
                    if (pre > ((4 - (st & 3)) & 3)) pre = (4 - (st & 3)) & 3;
                    if (g < pre) {
                        unsigned cv = __ldg(&colval[st + g]);
                        acc_edge(acc, cv, __ldg(&tin_v[(size_t)(cv & 0xFFFFu) * 8 + li]));
                    }
                    int e = st + pre;
                    const int nbatch = (en - e) >> 4;
                    uint4 cv;
                    if (nbatch > 0) cv = __ldg((const uint4*)&colval[e + 4 * g]);
                    for (int it = 0; it < nbatch; it++) {
                        uint2 r0 = __ldg(&tin_v[(size_t)(cv.x & 0xFFFFu) * 8 + li]);
                        uint2 r1 = __ldg(&tin_v[(size_t)(cv.y & 0xFFFFu) * 8 + li]);
                        uint2 r2 = __ldg(&tin_v[(size_t)(cv.z & 0xFFFFu) * 8 + li]);
                        uint2 r3 = __ldg(&tin_v[(size_t)(cv.w & 0xFFFFu) * 8 + li]);
                        uint4 cvn = cv;
                        if (it + 1 < nbatch)
                            cvn = __ldg((const uint4*)&colval[e + 16 * (it + 1) + 4 * g]);
                        acc_edge(acc, cv.x, r0);
                        acc_edge(acc, cv.y, r1);
                        acc_edge(acc, cv.z, r2);
                        acc_edge(acc, cv.w, r3);
                        cv = cvn;
                    }
                    e += nbatch << 4;
                    for (int ee = e + g; ee < en; ee += 4) {
                        unsigned cvs = __ldg(&colval[ee]);
                        acc_edge(acc, cvs, __ldg(&tin_v[(size_t)(cvs & 0xFFFFu) * 8 + li]));
                    }
#pragma unroll
                    for (int off = 8; off < 32; off <<= 1) {
                        acc.x += __shfl_xor_sync(0xffffffffu, acc.x, off);
                        acc.y += __shfl_xor_sync(0xffffffffu, acc.y, off);
                        acc.z += __shfl_xor_sync(0xffffffffu, acc.z, off);
                        acc.w += __shfl_xor_sync(0xffffffffu, acc.w, off);
                    }
                    {
                        const float dn = dis[r];
                        const float sn = dn * dn;
                        union { uint2 u; __half2 h[2]; } swv;
                        swv.u = __ldg(&tin_v[(size_t)r * 8 + li]);
                        float2 s01 = __half22float2(swv.h[0]);
                        float2 s23 = __half22float2(swv.h[1]);
                        acc.x += sn * s01.x; acc.y += sn * s01.y;
                        acc.z += sn * s23.x; acc.w += sn * s23.y;
                    }
                    if (g == 0) ((float4*)zbuf[wid])[li] = acc;
                    __syncwarp();
                    float u = 0.f;
                    {
                        const float4* zp = (const float4*)zbuf[wid];
                        const float4* wp = (const float4*)&Wt[lane * 36];
#pragma unroll
                        for (int q = 0; q < 8; q++) {
                            const float4 zq = zp[q];
                            const float4 wq = wp[q];
                            u += zq.x * wq.x + zq.y * wq.y + zq.z * wq.z + zq.w * wq.w;
                        }
                    }
                    __syncwarp();

                    const float k = fmaxf(u + bb, 0.f) * gate;
                    const int idx = r * 32 + lane;
                    const float xv = xw[idx];
                    float y;
                    if (s == 0) {
                        ksb[idx] = k;
                        y = xv + 0.5f * Hstep * k;
                    } else if (s == 1) {
                        ksb[idx] += 2.f * k;
                        y = xv + 0.5f * Hstep * k;
                    } else if (s == 2) {
                        ksb[idx] += 2.f * k;
                        y = xv + Hstep * k;
                    } else {
                        y = xv + (Hstep / 6.f) * (ksb[idx] + k);
                        if (final_out) out[boff + idx] = y;
                        else           xw[idx] = y;
                    }
                    if (!final_out) tout[idx] = __float2half(y);
                }
            }
            pin ^= 1;
            if (!final_out) grid_barrier();
        }
    }
}

// ---------------- host ----------------
extern "C" void kernel_launch(void* const* d_in, const int* in_sizes, int n_in,
                              void* d_out, int out_size) {
    const float* x0 = (const float*)d_in[0];
    const void* epos = d_in[1];
    const void* eneg = d_in[2];
    const float* Wp = (const float*)d_in[3];
    const float* bp = (const float*)d_in[4];
    const float* wtp = (const float*)d_in[5];
    const float* Wn = (const float*)d_in[6];
    const float* bn = (const float*)d_in[7];
    const float* wtn = (const float*)d_in[8];
    float* out = (float*)d_out;

    const int EB = 1184;

    k_probe_zero<<<196, 256>>>((const int*)epos);
    k_hist<<<2 * EB, 256>>>(epos, eneg);
    k_scan_dis<<<2, 1024>>>();
    k_scatter_init<<<2 * EB + 296, 256>>>(epos, eneg, x0, EB);
    k_ode<<<592, 256>>>(Wp, bp, wtp, Wn, bn, wtn, out);
}

// round 17
// speedup vs baseline: 1.1572x; 1.1572x over previous
#include <cuda_runtime.h>
#include <cuda_fp16.h>

#define NN 50000
#define NE 1600000
#define DD 32
static constexpr float Hstep = 0.1f;

// ---------------- static device scratch ----------------
__device__ int      g_is64;
__device__ int      g_deg[2][NN];
__device__ int      g_cur[2][NN];
__device__ int      g_rowptr[2][NN + 1];
__device__ __align__(16) unsigned g_colval[2][NE];   // low16 = col, high16 = fp16 val
__device__ float    g_dis[2][NN];
__device__ __align__(16) __half g_tmph[2][2 * NN * DD];  // ping-pong y buffers, both branches
__device__ __align__(128) float g_x[2 * NN * DD];
__device__ __align__(128) float g_ksum[2 * NN * DD];

// ---------------- edge readers (dtype-agnostic) ----------------
__device__ __forceinline__ int edge_src(const void* ei, int e, int is64) {
    if (is64) return (int)((const long long*)ei)[e];
    return ((const int*)ei)[e];
}
__device__ __forceinline__ int edge_dst(const void* ei, int e, int is64) {
    if (is64) return (int)((const long long*)ei)[NE + e];
    return ((const int*)ei)[NE + e];
}

// ---------------- setup: probe dtype + zero both degree arrays ----------------
__global__ void k_probe_zero(const int* __restrict__ w) {
    if (blockIdx.x == 0) {
        __shared__ int anynz;
        if (threadIdx.x == 0) anynz = 0;
        __syncthreads();
        if (w[2 * threadIdx.x + 1] != 0) atomicOr(&anynz, 1);
        __syncthreads();
        if (threadIdx.x == 0) g_is64 = (anynz == 0) ? 1 : 0;
    }
    int i = blockIdx.x * blockDim.x + threadIdx.x;
    int stride = gridDim.x * blockDim.x;
    for (; i < 2 * NN; i += stride) ((int*)g_deg)[i] = 0;
}

// both branches: blocks [0,H) -> pos, [H,2H) -> neg
__global__ void k_hist(const void* __restrict__ epos, const void* __restrict__ eneg) {
    const int H = gridDim.x >> 1;
    const int br = blockIdx.x >= H;
    const void* ei = br ? eneg : epos;
    const int bb = blockIdx.x - br * H;
    const int is64 = g_is64;
    int stride = H * blockDim.x;
    for (int e = bb * blockDim.x + threadIdx.x; e < NE; e += stride)
        atomicAdd(&g_deg[br][edge_dst(ei, e, is64)], 1);
}

// block b = branch b: dis + exclusive scan -> rowptr, cur
__global__ void k_scan_dis() {
    const int b = blockIdx.x;
    __shared__ int sm[1024];
    const int tid = threadIdx.x;
    const int CH = (NN + 1023) / 1024;  // 49
    int base = tid * CH;
    int s = 0;
    for (int i = 0; i < CH; i++) {
        int idx = base + i;
        if (idx < NN) {
            int d = g_deg[b][idx];
            g_dis[b][idx] = rsqrtf((float)d + 1.0f);
            s += d;
        }
    }
    sm[tid] = s;
    __syncthreads();
    for (int off = 1; off < 1024; off <<= 1) {
        int v = (tid >= off) ? sm[tid - off] : 0;
        __syncthreads();
        sm[tid] += v;
        __syncthreads();
    }
    int run = (tid == 0) ? 0 : sm[tid - 1];
    for (int i = 0; i < CH; i++) {
        int idx = base + i;
        if (idx < NN) {
            g_rowptr[b][idx] = run;
            g_cur[b][idx] = run;
            run += g_deg[b][idx];
        }
    }
    if (tid == 1023) g_rowptr[b][NN] = sm[1023];
}

// blocks [0,EB): scatter pos; [EB,2EB): scatter neg; rest: init x / tin
__global__ void __launch_bounds__(256) k_scatter_init(
    const void* __restrict__ epos, const void* __restrict__ eneg,
    const float* __restrict__ x0, int EB) {
    if (blockIdx.x < 2 * EB) {
        const int br = blockIdx.x >= EB;
        const void* ei = br ? eneg : epos;
        const int bb = blockIdx.x - br * EB;
        const int is64 = g_is64;
        int stride = EB * blockDim.x;
        for (int e = bb * blockDim.x + threadIdx.x; e < NE; e += stride) {
            int s = edge_src(ei, e, is64);
            int d = edge_dst(ei, e, is64);
            int p = atomicAdd(&g_cur[br][d], 1);
            __half hv = __float2half(g_dis[br][s] * g_dis[br][d]);
            g_colval[br][p] = (unsigned)s | ((unsigned)__half_as_ushort(hv) << 16);
        }
    } else {
        int i = (blockIdx.x - 2 * EB) * blockDim.x + threadIdx.x;
        int stride = (gridDim.x - 2 * EB) * blockDim.x;
        for (; i < 2 * NN * DD; i += stride) {
            float v = x0[i >= NN * DD ? i - NN * DD : i];
            g_x[i] = v;
            g_tmph[0][i] = __float2half(v);
        }
    }
}

__device__ __forceinline__ void acc_edge(float4& acc, unsigned cvw, const uint2 rw_u) {
    union { uint2 u; __half2 h[2]; } rw;
    rw.u = rw_u;
    const float v = __half2float(__ushort_as_half((unsigned short)(cvw >> 16)));
    float2 a01 = __half22float2(rw.h[0]);
    float2 a23 = __half22float2(rw.h[1]);
    acc.x += v * a01.x; acc.y += v * a01.y;
    acc.z += v * a23.x; acc.w += v * a23.y;
}

// ---------------- fused RK4 stage, both branches, deferred @W ----------------
// Gather raw y (fp16): z = sum v*y_src + selfnorm*y_r; u = z @ W;
// k = relu(u + b)*gate; RK4 update scalar-per-lane; store y' (fp16) to tout.
template <int STAGE>
__global__ void __launch_bounds__(256, 6) k_stage(
    int pin,
    const float* __restrict__ Wp, const float* __restrict__ bp, const float* __restrict__ wtp,
    const float* __restrict__ Wn, const float* __restrict__ bn, const float* __restrict__ wtn,
    float t, float* __restrict__ xout) {
    const int H = gridDim.x >> 1;
    const int br = blockIdx.x >= H;
    const float* __restrict__ W = br ? Wn : Wp;
    const float* __restrict__ bvec = br ? bn : bp;
    const float* __restrict__ wt = br ? wtn : wtp;
    const unsigned* __restrict__ colval = g_colval[br];
    const int* __restrict__ rowptr = g_rowptr[br];
    const float* __restrict__ dis = g_dis[br];
    const size_t boff = (size_t)br * NN * DD;
    const uint2* __restrict__ tin_v = (const uint2*)(g_tmph[pin]) + (size_t)br * NN * 8;
    __half* __restrict__ tout = g_tmph[pin ^ 1] + boff;
    const float* __restrict__ xbase = g_x + boff;
    float* __restrict__ xw = g_x + boff;
    float* __restrict__ ksb = g_ksum + boff;

    __shared__ float Wt[DD * 36];        // transposed W, row stride 36 floats
    __shared__ float zbuf[8][DD];
    {
        int tid = threadIdx.x;
        for (int idx = tid; idx < DD * DD; idx += 256) {
            int d = idx >> 5, l = idx & 31;
            Wt[l * 36 + d] = W[idx];
        }
    }
    __syncthreads();

    const int lane = threadIdx.x & 31;
    const int wid = threadIdx.x >> 5;
    const int li = lane & 7;
    const int g = lane >> 3;

    const float bb = __ldg(&bvec[lane]);
    const float gate = 1.0f / (1.0f + __expf(-t * __ldg(&wt[lane])));

    int warpLocal = (blockIdx.x - br * H) * 8 + wid;
    const int nwarps = H * 8;

    for (int r = warpLocal; r < NN; r += nwarps) {
        const int st = rowptr[r];
        const int en = rowptr[r + 1];
        float4 acc = make_float4(0.f, 0.f, 0.f, 0.f);

        // peel to 4-alignment (group g takes edge st+g)
        int pre = en - st;
        if (pre > ((4 - (st & 3)) & 3)) pre = (4 - (st & 3)) & 3;
        if (g < pre) {
            unsigned cv = __ldg(&colval[st + g]);
            acc_edge(acc, cv, __ldg(&tin_v[(size_t)(cv & 0xFFFFu) * 8 + li]));
        }
        int e = st + pre;
        const int nbatch = (en - e) >> 4;   // 16-edge batches
        // software-pipelined: colval for batch i+1 prefetched during batch i
        uint4 cv;
        if (nbatch > 0) cv = __ldg((const uint4*)&colval[e + 4 * g]);
        for (int it = 0; it < nbatch; it++) {
            uint2 r0 = __ldg(&tin_v[(size_t)(cv.x & 0xFFFFu) * 8 + li]);
            uint2 r1 = __ldg(&tin_v[(size_t)(cv.y & 0xFFFFu) * 8 + li]);
            uint2 r2 = __ldg(&tin_v[(size_t)(cv.z & 0xFFFFu) * 8 + li]);
            uint2 r3 = __ldg(&tin_v[(size_t)(cv.w & 0xFFFFu) * 8 + li]);
            uint4 cvn = cv;
            if (it + 1 < nbatch)
                cvn = __ldg((const uint4*)&colval[e + 16 * (it + 1) + 4 * g]);
            acc_edge(acc, cv.x, r0);
            acc_edge(acc, cv.y, r1);
            acc_edge(acc, cv.z, r2);
            acc_edge(acc, cv.w, r3);
            cv = cvn;
        }
        e += nbatch << 4;
        // remainder: group g takes every 4th
        for (int ee = e + g; ee < en; ee += 4) {
            unsigned cvs = __ldg(&colval[ee]);
            acc_edge(acc, cvs, __ldg(&tin_v[(size_t)(cvs & 0xFFFFu) * 8 + li]));
        }
        // combine 4 group partials (lanes with equal li)
#pragma unroll
        for (int off = 8; off < 32; off <<= 1) {
            acc.x += __shfl_xor_sync(0xffffffffu, acc.x, off);
            acc.y += __shfl_xor_sync(0xffffffffu, acc.y, off);
            acc.z += __shfl_xor_sync(0xffffffffu, acc.z, off);
            acc.w += __shfl_xor_sync(0xffffffffu, acc.w, off);
        }
        // self term (all lanes compute identically)
        {
            const float dn = dis[r];
            const float sn = dn * dn;
            union { uint2 u; __half2 h[2]; } swv;
            swv.u = __ldg(&tin_v[(size_t)r * 8 + li]);
            float2 s01 = __half22float2(swv.h[0]);
            float2 s23 = __half22float2(swv.h[1]);
            acc.x += sn * s01.x; acc.y += sn * s01.y;
            acc.z += sn * s23.x; acc.w += sn * s23.y;
        }
        // z -> smem (group 0), then per-lane u = z @ W[:,lane]
        if (g == 0) ((float4*)zbuf[wid])[li] = acc;
        __syncwarp();
        float u = 0.f;
        {
            const float4* zp = (const float4*)zbuf[wid];
            const float4* wp = (const float4*)&Wt[lane * 36];
#pragma unroll
            for (int q = 0; q < 8; q++) {
                const float4 zq = zp[q];
                const float4 wq = wp[q];
                u += zq.x * wq.x + zq.y * wq.y + zq.z * wq.z + zq.w * wq.w;
            }
        }
        __syncwarp();

        const float k = fmaxf(u + bb, 0.f) * gate;
        const int idx = r * 32 + lane;
        const float xv = xbase[idx];
        float y;
        if (STAGE == 1) {
            ksb[idx] = k;
            y = xv + 0.5f * Hstep * k;
        } else if (STAGE == 2) {
            ksb[idx] += 2.f * k;
            y = xv + 0.5f * Hstep * k;
        } else if (STAGE == 3) {
            ksb[idx] += 2.f * k;
            y = xv + Hstep * k;
        } else {
            y = xv + (Hstep / 6.f) * (ksb[idx] + k);
            if (xout) xout[boff + idx] = y;
            else      xw[idx] = y;
        }
        tout[idx] = __float2half(y);
    }
}

// ---------------- host ----------------
extern "C" void kernel_launch(void* const* d_in, const int* in_sizes, int n_in,
                              void* d_out, int out_size) {
    const float* x0 = (const float*)d_in[0];
    const void* epos = d_in[1];
    const void* eneg = d_in[2];
    const float* Wp = (const float*)d_in[3];
    const float* bp = (const float*)d_in[4];
    const float* wtp = (const float*)d_in[5];
    const float* Wn = (const float*)d_in[6];
    const float* bn = (const float*)d_in[7];
    const float* wtn = (const float*)d_in[8];
    float* out = (float*)d_out;

    const int STAGE_BLOCKS = 888;  // 6 blocks/SM x 148 SMs; 444 per branch
    const int EB = 1184;

    k_probe_zero<<<196, 256>>>((const int*)epos);
    k_hist<<<2 * EB, 256>>>(epos, eneg);
    k_scan_dis<<<2, 1024>>>();
    k_scatter_init<<<2 * EB + 296, 256>>>(epos, eneg, x0, EB);

    int pin = 0;
    for (int step = 0; step < 10; step++) {
        float t = step * Hstep;
        k_stage<1><<<STAGE_BLOCKS, 256>>>(pin, Wp, bp, wtp, Wn, bn, wtn, t, nullptr);
        pin ^= 1;
        k_stage<2><<<STAGE_BLOCKS, 256>>>(pin, Wp, bp, wtp, Wn, bn, wtn, t + 0.5f * Hstep, nullptr);
        pin ^= 1;
        k_stage<3><<<STAGE_BLOCKS, 256>>>(pin, Wp, bp, wtp, Wn, bn, wtn, t + 0.5f * Hstep, nullptr);
        pin ^= 1;
        float* xo = (step == 9) ? out : nullptr;
        k_stage<4><<<STAGE_BLOCKS, 256>>>(pin, Wp, bp, wtp, Wn, bn, wtn, t + Hstep, xo);
        pin ^= 1;
    }
}